// round 10
// baseline (speedup 1.0000x reference)
#include <cuda_runtime.h>
#include <cuda_bf16.h>

// OccupancyGridForestAS: 4.19M points, 8x8x8 block lookup -> 64 trees of 64^3 voxels.
//
// inputs (metadata order):
//   d_in[0]: pts            float32 [N_PTS, 3]
//   d_in[1]: occ_val_grid   float32 [64, 64, 64, 64]
//   d_in[2]: block_lookup   int32   [8, 8, 8]
// output: float32 [N_PTS]
//
// R10: R9's 8-pt/iter persistent loop, but with __launch_bounds__(256, 8) to
// pin regs <=32 (R9's 34 regs rounded to 40 -> only 6 blocks/SM = 65% occ).
// This keeps 2x gather/stream MLP at FULL occupancy. Grid = nsm*8 so every
// SM gets exactly 8 blocks (R8's 1184 on 152 SMs left a 12.5% block
// imbalance on 32 SMs). Cache policy = proven config.

#define RES   64
#define LDIM  8
#define NTHREADS 256

__global__ void __launch_bounds__(NTHREADS, 8)
occ_forest_kernel(const float4* __restrict__ pts4,
                  const float*  __restrict__ occ,
                  const int*    __restrict__ lut,
                  float4*       __restrict__ out4,
                  int nc)                      // number of 8-point chunks
{
    __shared__ int s_lut[LDIM * LDIM * LDIM];  // 512 ints = 2KB
    {
        int tid = threadIdx.x;
        s_lut[tid]       = lut[tid];
        s_lut[tid + 256] = lut[tid + 256];
    }
    __syncthreads();

    const int stride = gridDim.x * blockDim.x;

    for (int t = blockIdx.x * blockDim.x + threadIdx.x; t < nc; t += stride) {
        // 8 points = 24 floats = 6 float4, issued back-to-back (MLP_p1 = 6)
        float4 v0 = __ldcs(&pts4[6 * t + 0]);
        float4 v1 = __ldcs(&pts4[6 * t + 1]);
        float4 v2 = __ldcs(&pts4[6 * t + 2]);
        float4 v3 = __ldcs(&pts4[6 * t + 3]);
        float4 v4 = __ldcs(&pts4[6 * t + 4]);
        float4 v5 = __ldcs(&pts4[6 * t + 5]);

        // point i -> (x,y,z) component mapping of the 6 float4s
        float px[8] = {v0.x, v0.w, v1.z, v2.y, v3.x, v3.w, v4.z, v5.y};
        float py[8] = {v0.y, v1.x, v1.w, v2.z, v3.y, v4.x, v4.w, v5.z};
        float pz[8] = {v0.z, v1.y, v2.x, v2.w, v3.z, v4.y, v5.x, v5.w};

        int  idx[8];
        bool valid[8];

        // Phase 1: index math for all 8 points (no cross-point dependencies)
#pragma unroll
        for (int i = 0; i < 8; i++) {
            float x = px[i], y = py[i], z = pz[i];

            int bx = (int)floorf(x);
            int by = (int)floorf(y);
            int bz = (int)floorf(z);

            bool in_dom = (bx >= 0) & (bx < LDIM) &
                          (by >= 0) & (by < LDIM) &
                          (bz >= 0) & (bz < LDIM);

            int cx = min(max(bx, 0), LDIM - 1);
            int cy = min(max(by, 0), LDIM - 1);
            int cz = min(max(bz, 0), LDIM - 1);

            int bidx = s_lut[cx * (LDIM * LDIM) + cy * LDIM + cz];
            valid[i] = in_dom && (bidx >= 0);

            // Bit-exact reference float sequence:
            //   block_x = 2*(p - bcs) - 1 ; vox = floor((block_x*0.5+0.5)*RES)
            // valid => x-cx in [0,1) => vox in [0,63]; clamps elided
            // (invalid points never issue the load).
            float bxf = 2.0f * (x - (float)cx) - 1.0f;
            float byf = 2.0f * (y - (float)cy) - 1.0f;
            float bzf = 2.0f * (z - (float)cz) - 1.0f;

            int vx = (int)floorf((bxf * 0.5f + 0.5f) * (float)RES);
            int vy = (int)floorf((byf * 0.5f + 0.5f) * (float)RES);
            int vz = (int)floorf((bzf * 0.5f + 0.5f) * (float)RES);

            idx[i] = bidx * (RES * RES * RES) + vx * (RES * RES) + vy * RES + vz;
        }

        // Phase 2: 8 independent predicated gathers (L2-only path)
        float r[8];
#pragma unroll
        for (int i = 0; i < 8; i++)
            r[i] = valid[i] ? __ldcg(&occ[idx[i]]) : 0.0f;

        float4 o0, o1;
        o0.x = r[0]; o0.y = r[1]; o0.z = r[2]; o0.w = r[3];
        o1.x = r[4]; o1.y = r[5]; o1.z = r[6]; o1.w = r[7];
        __stcs(&out4[2 * t + 0], o0);
        __stcs(&out4[2 * t + 1], o1);
    }
}

extern "C" void kernel_launch(void* const* d_in, const int* in_sizes, int n_in,
                              void* d_out, int out_size)
{
    const float4* pts4 = (const float4*)d_in[0];
    const float*  occ  = (const float*)d_in[1];
    const int*    lut  = (const int*)d_in[2];
    float4*       out  = (float4*)d_out;

    int n_pts = in_sizes[0] / 3;       // 4,194,304
    int nc    = n_pts / 8;             // 524,288 8-point chunks

    int dev = 0, nsm = 148;
    cudaGetDevice(&dev);
    cudaDeviceGetAttribute(&nsm, cudaDevAttrMultiProcessorCount, dev);

    int blocks = nsm * 8;              // exactly 8 blocks on every SM
    occ_forest_kernel<<<blocks, NTHREADS>>>(pts4, occ, lut, out, nc);
}

// round 11
// speedup vs baseline: 1.2569x; 1.2569x over previous
#include <cuda_runtime.h>
#include <cuda_bf16.h>

// OccupancyGridForestAS: 4.19M points, 8x8x8 block lookup -> 64 trees of 64^3 voxels.
//
// inputs (metadata order):
//   d_in[0]: pts            float32 [N_PTS, 3]
//   d_in[1]: occ_val_grid   float32 [64, 64, 64, 64]
//   d_in[2]: block_lookup   int32   [8, 8, 8]
// output: float32 [N_PTS]
//
// R11: champion R8 body (4 pts/iter, 32 regs, no spills) with the grid fixed
// for the ACTUAL SM count discovered in R9: 152 SMs -> 1216 blocks so every
// SM carries exactly 8 equal-work blocks (R8's 1184 left 32 SMs at 7 blocks,
// making the 8-block SMs the ~14%-longer critical path).
// Cache policy: __ldcs stream / __ldcg gather / __stcs out (proven in R5/R6).

#define RES   64
#define LDIM  8
#define NTHREADS 256

__global__ void __launch_bounds__(NTHREADS)
occ_forest_kernel(const float4* __restrict__ pts4,
                  const float*  __restrict__ occ,
                  const int*    __restrict__ lut,
                  float4*       __restrict__ out4,
                  int nc)                      // number of 4-point chunks
{
    __shared__ int s_lut[LDIM * LDIM * LDIM];  // 512 ints = 2KB
    {
        int tid = threadIdx.x;
        s_lut[tid]       = lut[tid];
        s_lut[tid + 256] = lut[tid + 256];
    }
    __syncthreads();

    const int stride = gridDim.x * blockDim.x;

    for (int t = blockIdx.x * blockDim.x + threadIdx.x; t < nc; t += stride) {
        // 4 points = 12 floats = 3 float4 (coalesced, evict-first in L2)
        float4 a = __ldcs(&pts4[3 * t + 0]);
        float4 b = __ldcs(&pts4[3 * t + 1]);
        float4 c = __ldcs(&pts4[3 * t + 2]);

        float px[4] = {a.x, a.w, b.z, c.y};
        float py[4] = {a.y, b.x, b.w, c.z};
        float pz[4] = {a.z, b.y, c.x, c.w};

        int  idx[4];
        bool valid[4];

        // Phase 1: index math for all 4 points (no cross-point dependencies)
#pragma unroll
        for (int i = 0; i < 4; i++) {
            float x = px[i], y = py[i], z = pz[i];

            int bx = (int)floorf(x);
            int by = (int)floorf(y);
            int bz = (int)floorf(z);

            bool in_dom = (bx >= 0) & (bx < LDIM) &
                          (by >= 0) & (by < LDIM) &
                          (bz >= 0) & (bz < LDIM);

            int cx = min(max(bx, 0), LDIM - 1);
            int cy = min(max(by, 0), LDIM - 1);
            int cz = min(max(bz, 0), LDIM - 1);

            int bidx = s_lut[cx * (LDIM * LDIM) + cy * LDIM + cz];
            valid[i] = in_dom && (bidx >= 0);

            // Bit-exact reference float sequence:
            //   block_x = 2*(p - bcs) - 1 ; vox = floor((block_x*0.5+0.5)*RES)
            // valid => x-cx in [0,1) => vox in [0,63]; clamps elided
            // (invalid points never issue the load).
            float bxf = 2.0f * (x - (float)cx) - 1.0f;
            float byf = 2.0f * (y - (float)cy) - 1.0f;
            float bzf = 2.0f * (z - (float)cz) - 1.0f;

            int vx = (int)floorf((bxf * 0.5f + 0.5f) * (float)RES);
            int vy = (int)floorf((byf * 0.5f + 0.5f) * (float)RES);
            int vz = (int)floorf((bzf * 0.5f + 0.5f) * (float)RES);

            idx[i] = bidx * (RES * RES * RES) + vx * (RES * RES) + vy * RES + vz;
        }

        // Phase 2: 4 independent predicated gathers (L2-only path)
        float r[4];
#pragma unroll
        for (int i = 0; i < 4; i++)
            r[i] = valid[i] ? __ldcg(&occ[idx[i]]) : 0.0f;

        float4 o;
        o.x = r[0]; o.y = r[1]; o.z = r[2]; o.w = r[3];
        __stcs(&out4[t], o);
    }
}

extern "C" void kernel_launch(void* const* d_in, const int* in_sizes, int n_in,
                              void* d_out, int out_size)
{
    const float4* pts4 = (const float4*)d_in[0];
    const float*  occ  = (const float*)d_in[1];
    const int*    lut  = (const int*)d_in[2];
    float4*       out  = (float4*)d_out;

    int n_pts = in_sizes[0] / 3;       // 4,194,304
    int nc    = n_pts / 4;             // 1,048,576 4-point chunks

    int dev = 0, nsm = 152;
    cudaGetDevice(&dev);
    cudaDeviceGetAttribute(&nsm, cudaDevAttrMultiProcessorCount, dev);

    int blocks = nsm * 8;              // exactly 8 equal-work blocks per SM
    occ_forest_kernel<<<blocks, NTHREADS>>>(pts4, occ, lut, out, nc);
}